// round 5
// baseline (speedup 1.0000x reference)
#include <cuda_runtime.h>
#include <stdint.h>

#define HH 1024
#define WW 2048
#define HW (HH * WW)              // 2,097,152 pixels
#define NI 128                    // instances
#define NB 10                     // "thing" classes 24..33
#define NBINS (NI * NB)           // 1280
#define THREADS 256
#define NGRP (HW / 4)             // 524,288 four-pixel groups
#define NBLK_STATS (NGRP / THREADS)            // 2048 stats blocks
#define NQ ((size_t)NI * HW / 4)               // float4 count of mask region
#define NBLK_ZERO ((int)(NQ / THREADS))        // 262,144 zero-fill blocks
#define NBLK_A (NBLK_STATS + NBLK_ZERO)
#define NBLK_SCAT (HW / 16 / THREADS)          // 512 scatter blocks (16 px/thread)

// Scratch (no cudaMalloc allowed). Bins + ticket are reset by the last stats
// block every run; g_inst8 is fully rewritten every run. Deterministic
// across graph replays.
__device__ uint8_t      g_inst8[HW];     // per-pixel instance id (0 = stuff)
__device__ int          g_counts[NBINS];
__device__ float        g_sums[NBINS];
__device__ unsigned int g_done;

// ---------------------------------------------------------------------------
// Kernel A: fused zero-fill + stats + finalize.
//   blocks [0, 2048): stats prepass
//     - inst = (24 <= seg <= 33) ? instance_maps : 0  -> g_inst8 (uchar4)
//     - shared-mem histograms -> RED flush to global bins
//     - ticket among stats blocks: the LAST stats block computes the 5 tail
//       outputs and resets the bins/ticket (all hidden under the fill wave).
//   blocks [2048, NBLK_A): pure float4 streaming zero-fill of the 1.073 GB
//     mask region (dependency-free stores -> DRAM write roofline).
// ---------------------------------------------------------------------------
__global__ void __launch_bounds__(THREADS)
fill_stats_kernel(const int4*   __restrict__ seg4,
                  const int4*   __restrict__ inst4,
                  const float4* __restrict__ probs4,
                  const float*  __restrict__ inst_probs,
                  float4*       __restrict__ out4) {
    const int tid = threadIdx.x;
    const int b   = blockIdx.x;

    if (b >= NBLK_STATS) {
        // ---------------- zero-fill path (pure streaming stores) ----------
        const size_t i = (size_t)(b - NBLK_STATS) * THREADS + tid;
        __stcs(&out4[i], make_float4(0.f, 0.f, 0.f, 0.f));
        return;
    }

    // -------------------- stats path ------------------------------------
    __shared__ int          s_cnt[NBINS];
    __shared__ float        s_sum[NBINS];
    __shared__ unsigned int s_ticket;

    for (int i = tid; i < NBINS; i += THREADS) { s_cnt[i] = 0; s_sum[i] = 0.0f; }
    __syncthreads();

    const int t = b * THREADS + tid;                // 4-pixel group index

    const int4 sg = seg4[t];
    const int4 im = inst4[t];
    const int ss[4] = { sg.x, sg.y, sg.z, sg.w };
    const int iv[4] = { im.x, im.y, im.z, im.w };
    int ii[4];

    #pragma unroll
    for (int j = 0; j < 4; ++j) {
        const int s = ss[j];
        const int inst = (s >= 24 && s <= 33) ? iv[j] : 0;
        ii[j] = inst;
        if (inst > 0)
            atomicAdd(&s_cnt[(inst - 1) * NB + (s - 24)], 1);
    }

    uchar4 packed;
    packed.x = (uint8_t)ii[0];
    packed.y = (uint8_t)ii[1];
    packed.z = (uint8_t)ii[2];
    packed.w = (uint8_t)ii[3];
    ((uchar4*)g_inst8)[t] = packed;

    if (ii[0] | ii[1] | ii[2] | ii[3]) {
        #pragma unroll
        for (int c = 0; c < NB; ++c) {
            const float4 pv = __ldg(&probs4[(size_t)(24 + c) * NGRP + t]);
            const float pa[4] = { pv.x, pv.y, pv.z, pv.w };
            #pragma unroll
            for (int j = 0; j < 4; ++j)
                if (ii[j] > 0)
                    atomicAdd(&s_sum[(ii[j] - 1) * NB + c], pa[j]);
        }
    }

    __syncthreads();
    for (int i = tid; i < NBINS; i += THREADS) {
        const int   cv = s_cnt[i];
        const float sv = s_sum[i];
        if (cv)          atomicAdd(&g_counts[i], cv);
        if (sv != 0.0f)  atomicAdd(&g_sums[i], sv);
    }

    // ---- ticket among stats blocks only; last one finalizes ----
    __threadfence();                   // publish this block's RED results
    __syncthreads();
    if (tid == 0)
        s_ticket = atomicAdd(&g_done, 1u);
    __syncthreads();

    if (s_ticket == (unsigned)(NBLK_STATS - 1)) {
        float* out = (float*)out4;
        if (tid < NI) {
            const int i = tid;
            int tot = 0, best = 0, bestc = 0;
            #pragma unroll
            for (int c = 0; c < NB; ++c) {
                const int v = __ldcg(&g_counts[i * NB + c]);
                tot += v;
                if (v > best) { best = v; bestc = c; }   // first-occurrence ties
            }
            float cls = 0.0f, segp = 0.0f;
            if (tot > 0) {
                cls  = (float)(24 + bestc);
                segp = __ldcg(&g_sums[i * NB + bestc]) / (float)tot;
            }
            float* tail = out + (size_t)NI * HW;
            tail[0 * NI + i] = cls;                      // inst_class
            tail[1 * NI + i] = inst_probs[i];            // instance_probs
            tail[2 * NI + i] = segp;                     // seg_prob
            tail[3 * NI + i] = (float)tot;               // total
            tail[4 * NI + i] = (tot > 0) ? 1.0f : 0.0f;  // valid
        }
        __syncthreads();
        // Reset scratch for the next graph replay.
        for (int i = tid; i < NBINS; i += THREADS) {
            g_counts[i] = 0;
            g_sums[i]   = 0.0f;
        }
        if (tid == 0) g_done = 0u;
    }
}

// ---------------------------------------------------------------------------
// Kernel B: pure sparse scatter, MLP-optimized.
//   Each thread loads 16 packed instance ids with ONE coalesced uint4 load
//   (front-batched -> latency amortized), then issues up to 16 INDEPENDENT
//   4-byte stores of 1.0f at out[(id-1)*HW + pixel]. 512 blocks.
// ---------------------------------------------------------------------------
__global__ void __launch_bounds__(THREADS)
scatter_kernel(float* __restrict__ out) {
    const int t  = blockIdx.x * THREADS + threadIdx.x;   // 16-pixel group
    const int p0 = t * 16;

    const uint4 w = ((const uint4*)g_inst8)[t];
    const unsigned int ws[4] = { w.x, w.y, w.z, w.w };

    #pragma unroll
    for (int q = 0; q < 4; ++q) {
        const unsigned int v = ws[q];
        if (v == 0u) continue;                // ~25% of words are all-stuff
        #pragma unroll
        for (int bb = 0; bb < 4; ++bb) {
            const int id = (v >> (8 * bb)) & 0xFF;
            if (id)
                out[(size_t)(id - 1) * HW + p0 + q * 4 + bb] = 1.0f;
        }
    }
}

// ---------------------------------------------------------------------------
extern "C" void kernel_launch(void* const* d_in, const int* in_sizes, int n_in,
                              void* d_out, int out_size) {
    const int*   seg    = (const int*)  d_in[0];   // (H, W) int32
    const int*   inst   = (const int*)  d_in[1];   // (H, W) int32
    const float* probs  = (const float*)d_in[2];   // (C, H, W) float32
    const float* iprobs = (const float*)d_in[3];   // (128,) float32
    float* out = (float*)d_out;

    fill_stats_kernel<<<NBLK_A, THREADS>>>(
        (const int4*)seg, (const int4*)inst, (const float4*)probs, iprobs,
        (float4*)out);
    scatter_kernel<<<NBLK_SCAT, THREADS>>>(out);
}